// round 2
// baseline (speedup 1.0000x reference)
#include <cuda_runtime.h>
#include <cstdint>

// Problem constants
#define T_DIM  1024
#define B_DIM  8
#define IN_DIM 512
#define D_DIM  64
#define N_DIM  64
#define EPS    1e-8f
#define NCHUNK 32
#define CHUNK  32               // T_DIM / NCHUNK
#define ROWS   (T_DIM * B_DIM)  // 8192
#define PROJ_ELEMS (ROWS * 64)  // 524288 per projection

// Scratch (device globals: no allocation allowed)
__device__ float g_V[PROJ_ELEMS];
__device__ float g_K[PROJ_ELEMS];
__device__ float g_A[PROJ_ELEMS];
__device__ float g_P[PROJ_ELEMS];
__device__ float g_invP[PROJ_ELEMS];
__device__ float g_chunkProd[NCHUNK * B_DIM * N_DIM];     // 16384
__device__ float g_chunkPrefix[NCHUNK * B_DIM * N_DIM];   // 16384
__device__ float g_Csum[NCHUNK * B_DIM * D_DIM * N_DIM];  // 1M floats (4MB)

typedef unsigned long long ull;

__device__ __forceinline__ ull pack2(float lo, float hi) {
    ull r; asm("mov.b64 %0, {%1, %2};" : "=l"(r) : "f"(lo), "f"(hi)); return r;
}
__device__ __forceinline__ void unpack2(ull v, float& lo, float& hi) {
    asm("mov.b64 {%0, %1}, %2;" : "=f"(lo), "=f"(hi) : "l"(v));
}
__device__ __forceinline__ void fma2(ull& d, ull a, ull b) {
    asm("fma.rn.f32x2 %0, %1, %2, %0;" : "+l"(d) : "l"(a), "l"(b));
}

// ---------------------------------------------------------------------------
// K1: projections. y = x @ W^T + b  for Wv, Wk, Wa (blockIdx.y selects).
// BM=64 rows, 64 cols, BK=16. 128 threads: 16 row-groups x 8 col-groups,
// each thread computes 4 rows x 8 cols = 16 packed f32x2 accumulators.
// x is stored DUPLICATED in smem ((x,x) pairs) so the inner loop issues
// zero packing movs: 8 LDS.64 + 16 FFMA2 per k-step.
// ---------------------------------------------------------------------------
__global__ void proj_kernel(const float* __restrict__ x,
                            const float* __restrict__ Wv, const float* __restrict__ bv,
                            const float* __restrict__ Wk, const float* __restrict__ bk,
                            const float* __restrict__ Wa, const float* __restrict__ ba)
{
    __shared__ float xs2[16][130];   // duplicated x: [kk][2*r+{0,1}]
    __shared__ float ws[16][72];     // [kk][c]

    const int m = blockIdx.y;
    const float* __restrict__ W    = (m == 0) ? Wv : (m == 1) ? Wk : Wa;
    const float* __restrict__ bias = (m == 0) ? bv : (m == 1) ? bk : ba;
    float* __restrict__ out        = (m == 0) ? g_V : (m == 1) ? g_K : g_A;

    const int row0 = blockIdx.x * 64;
    const int tid  = threadIdx.x;       // 0..127
    const int cg   = tid & 7;           // col group
    const int rg   = tid >> 3;          // row group (0..15)
    const int r_base = rg * 4;
    const int c_base = cg * 8;

    const int lr = tid >> 1;            // 0..63 (row for x load / col for w load)
    const int lk = (tid & 1) * 8;       // 0 or 8

    ull acc[4][4];
    #pragma unroll
    for (int i = 0; i < 4; i++)
        #pragma unroll
        for (int j = 0; j < 4; j++) acc[i][j] = 0ull;

    #pragma unroll 1
    for (int k0 = 0; k0 < IN_DIM; k0 += 16) {
        // load x rows (duplicated store)
        float4 a0 = *(const float4*)&x[(row0 + lr) * IN_DIM + k0 + lk];
        float4 a1 = *(const float4*)&x[(row0 + lr) * IN_DIM + k0 + lk + 4];
        *(ull*)&xs2[lk + 0][2 * lr] = pack2(a0.x, a0.x);
        *(ull*)&xs2[lk + 1][2 * lr] = pack2(a0.y, a0.y);
        *(ull*)&xs2[lk + 2][2 * lr] = pack2(a0.z, a0.z);
        *(ull*)&xs2[lk + 3][2 * lr] = pack2(a0.w, a0.w);
        *(ull*)&xs2[lk + 4][2 * lr] = pack2(a1.x, a1.x);
        *(ull*)&xs2[lk + 5][2 * lr] = pack2(a1.y, a1.y);
        *(ull*)&xs2[lk + 6][2 * lr] = pack2(a1.z, a1.z);
        *(ull*)&xs2[lk + 7][2 * lr] = pack2(a1.w, a1.w);
        // load W rows (c = lr)
        float4 b0 = *(const float4*)&W[lr * IN_DIM + k0 + lk];
        float4 b1 = *(const float4*)&W[lr * IN_DIM + k0 + lk + 4];
        ws[lk + 0][lr] = b0.x; ws[lk + 1][lr] = b0.y;
        ws[lk + 2][lr] = b0.z; ws[lk + 3][lr] = b0.w;
        ws[lk + 4][lr] = b1.x; ws[lk + 5][lr] = b1.y;
        ws[lk + 6][lr] = b1.z; ws[lk + 7][lr] = b1.w;
        __syncthreads();

        #pragma unroll
        for (int kk = 0; kk < 16; kk++) {
            ull xd0 = *(const ull*)&xs2[kk][2 * (r_base + 0)];
            ull xd1 = *(const ull*)&xs2[kk][2 * (r_base + 1)];
            ull xd2 = *(const ull*)&xs2[kk][2 * (r_base + 2)];
            ull xd3 = *(const ull*)&xs2[kk][2 * (r_base + 3)];
            ull w0  = *(const ull*)&ws[kk][c_base + 0];
            ull w1  = *(const ull*)&ws[kk][c_base + 2];
            ull w2  = *(const ull*)&ws[kk][c_base + 4];
            ull w3  = *(const ull*)&ws[kk][c_base + 6];
            fma2(acc[0][0], xd0, w0); fma2(acc[0][1], xd0, w1);
            fma2(acc[0][2], xd0, w2); fma2(acc[0][3], xd0, w3);
            fma2(acc[1][0], xd1, w0); fma2(acc[1][1], xd1, w1);
            fma2(acc[1][2], xd1, w2); fma2(acc[1][3], xd1, w3);
            fma2(acc[2][0], xd2, w0); fma2(acc[2][1], xd2, w1);
            fma2(acc[2][2], xd2, w2); fma2(acc[2][3], xd2, w3);
            fma2(acc[3][0], xd3, w0); fma2(acc[3][1], xd3, w1);
            fma2(acc[3][2], xd3, w2); fma2(acc[3][3], xd3, w3);
        }
        __syncthreads();
    }

    float bb[8];
    #pragma unroll
    for (int j = 0; j < 8; j++) bb[j] = bias[c_base + j];

    #pragma unroll
    for (int i = 0; i < 4; i++) {
        float s[8];
        #pragma unroll
        for (int j = 0; j < 4; j++) {
            unpack2(acc[i][j], s[2 * j], s[2 * j + 1]);
        }
        #pragma unroll
        for (int j = 0; j < 8; j++) s[j] += bb[j];
        if (m == 2) {   // alpha = sigmoid
            #pragma unroll
            for (int j = 0; j < 8; j++) s[j] = 1.0f / (1.0f + expf(-s[j]));
        }
        int o = (row0 + r_base + i) * 64 + c_base;
        *(float4*)&out[o]     = make_float4(s[0], s[1], s[2], s[3]);
        *(float4*)&out[o + 4] = make_float4(s[4], s[5], s[6], s[7]);
    }
}

// ---------------------------------------------------------------------------
// K2: per-chunk alpha products. 16384 threads = (chunk c, b*64+n).
// ---------------------------------------------------------------------------
__global__ void chunkprod_kernel()
{
    int idx = blockIdx.x * blockDim.x + threadIdx.x;  // 0..16383
    int c  = idx >> 9;
    int bn = idx & 511;
    const float* __restrict__ a = g_A + (c * CHUNK) * 512 + bn;
    float p = 1.0f;
    #pragma unroll
    for (int i = 0; i < CHUNK; i++) p *= a[i * 512];
    g_chunkProd[idx] = p;
}

// ---------------------------------------------------------------------------
// K3: exclusive scan of chunk products over c. 512 threads (one per (b,n)).
// ---------------------------------------------------------------------------
__global__ void chunkscan_kernel()
{
    int bn = threadIdx.x;  // 0..511
    float p = 1.0f;
    #pragma unroll
    for (int c = 0; c < NCHUNK; c++) {
        float v = g_chunkProd[c * 512 + bn];
        g_chunkPrefix[c * 512 + bn] = p;
        p *= v;
    }
}

// ---------------------------------------------------------------------------
// K4: full P = cumprod(alpha) and invP = 1/(P+eps).
// ---------------------------------------------------------------------------
__global__ void pcompute_kernel()
{
    int idx = blockIdx.x * blockDim.x + threadIdx.x;  // 0..16383
    int c  = idx >> 9;
    int bn = idx & 511;
    float p = g_chunkPrefix[idx];
    const float* __restrict__ a = g_A + (c * CHUNK) * 512 + bn;
    float* __restrict__ Pout    = g_P    + (c * CHUNK) * 512 + bn;
    float* __restrict__ iPout   = g_invP + (c * CHUNK) * 512 + bn;
    #pragma unroll
    for (int i = 0; i < CHUNK; i++) {
        p *= a[i * 512];
        Pout[i * 512]  = p;
        iPout[i * 512] = 1.0f / (p + EPS);
    }
}

// ---------------------------------------------------------------------------
// K5: per-chunk partial sums of v*k*invP per (b,d,n).
// grid 1024 = (c<<5)|(b<<2)|dt, block 256 = (d_local<<4)|ngroup.
// ---------------------------------------------------------------------------
__global__ void csum_kernel()
{
    int cb = blockIdx.x;
    int dt = cb & 3;
    int b  = (cb >> 2) & 7;
    int c  = cb >> 5;
    int d  = dt * 16 + (threadIdx.x >> 4);
    int n0 = (threadIdx.x & 15) * 4;

    float C0 = 0.f, C1 = 0.f, C2 = 0.f, C3 = 0.f;
    int t0 = c * CHUNK;
    #pragma unroll 4
    for (int i = 0; i < CHUNK; i++) {
        int base = ((t0 + i) * B_DIM + b) * 64;
        float  v  = g_V[base + d];
        float4 kk = *(const float4*)&g_K[base + n0];
        float4 ip = *(const float4*)&g_invP[base + n0];
        C0 = fmaf(v * kk.x, ip.x, C0);
        C1 = fmaf(v * kk.y, ip.y, C1);
        C2 = fmaf(v * kk.z, ip.z, C2);
        C3 = fmaf(v * kk.w, ip.w, C3);
    }
    int o = ((c * B_DIM + b) * D_DIM + d) * N_DIM + n0;
    *(float4*)&g_Csum[o] = make_float4(C0, C1, C2, C3);
}

// ---------------------------------------------------------------------------
// K6: in-place exclusive scan of g_Csum over chunk dim. 32768 threads.
// ---------------------------------------------------------------------------
__global__ void cscan_kernel()
{
    int bdn = blockIdx.x * blockDim.x + threadIdx.x;  // 0..32767
    float run = 0.0f;
    #pragma unroll
    for (int c = 0; c < NCHUNK; c++) {
        int off = c * (B_DIM * D_DIM * N_DIM) + bdn;
        float v = g_Csum[off];
        g_Csum[off] = run;
        run += v;
    }
}

// ---------------------------------------------------------------------------
// K7: final recurrence + output writes. Same grid decode as K5.
// out = [ spk (T*B*4096) | mem (T*B*4096) ]
// ---------------------------------------------------------------------------
__global__ void final_kernel(float* __restrict__ out)
{
    int cb = blockIdx.x;
    int dt = cb & 3;
    int b  = (cb >> 2) & 7;
    int c  = cb >> 5;
    int d  = dt * 16 + (threadIdx.x >> 4);
    int n0 = (threadIdx.x & 15) * 4;

    float* __restrict__ spk = out;
    float* __restrict__ mem = out + (size_t)T_DIM * B_DIM * 4096;

    int co = ((c * B_DIM + b) * D_DIM + d) * N_DIM + n0;
    float4 C = *(const float4*)&g_Csum[co];

    int t0 = c * CHUNK;
    #pragma unroll 4
    for (int i = 0; i < CHUNK; i++) {
        int t    = t0 + i;
        int base = (t * B_DIM + b) * 64;
        float  v  = g_V[base + d];
        float4 kk = *(const float4*)&g_K[base + n0];
        float4 ip = *(const float4*)&g_invP[base + n0];
        float4 P4 = *(const float4*)&g_P[base + n0];

        C.x = fmaf(v * kk.x, ip.x, C.x);
        C.y = fmaf(v * kk.y, ip.y, C.y);
        C.z = fmaf(v * kk.z, ip.z, C.z);
        C.w = fmaf(v * kk.w, ip.w, C.w);

        float4 S;
        S.x = C.x * P4.x; S.y = C.y * P4.y;
        S.z = C.z * P4.z; S.w = C.w * P4.w;

        float4 Sp;
        Sp.x = (S.x > 1.0f) ? 1.0f : 0.0f;
        Sp.y = (S.y > 1.0f) ? 1.0f : 0.0f;
        Sp.z = (S.z > 1.0f) ? 1.0f : 0.0f;
        Sp.w = (S.w > 1.0f) ? 1.0f : 0.0f;

        int o = (t * B_DIM + b) * 4096 + d * 64 + n0;
        *(float4*)&mem[o] = S;
        *(float4*)&spk[o] = Sp;
    }
}

// ---------------------------------------------------------------------------
extern "C" void kernel_launch(void* const* d_in, const int* in_sizes, int n_in,
                              void* d_out, int out_size)
{
    const float* x  = (const float*)d_in[0];
    const float* Wv = (const float*)d_in[1];
    const float* bv = (const float*)d_in[2];
    const float* Wk = (const float*)d_in[3];
    const float* bk = (const float*)d_in[4];
    const float* Wa = (const float*)d_in[5];
    const float* ba = (const float*)d_in[6];
    float* out = (float*)d_out;

    proj_kernel<<<dim3(ROWS / 64, 3), 128>>>(x, Wv, bv, Wk, bk, Wa, ba);
    chunkprod_kernel<<<64, 256>>>();
    chunkscan_kernel<<<1, 512>>>();
    pcompute_kernel<<<64, 256>>>();
    csum_kernel<<<NCHUNK * B_DIM * 4, 256>>>();
    cscan_kernel<<<128, 256>>>();
    final_kernel<<<NCHUNK * B_DIM * 4, 256>>>(out);
}

// round 10
// speedup vs baseline: 1.0193x; 1.0193x over previous
#include <cuda_runtime.h>
#include <cstdint>

// Problem constants
#define T_DIM  1024
#define B_DIM  8
#define IN_DIM 512
#define D_DIM  64
#define N_DIM  64
#define EPS    1e-8f
#define NCHUNK 32
#define CHUNK  32               // T_DIM / NCHUNK
#define ROWS   (T_DIM * B_DIM)  // 8192
#define PROJ_ELEMS (ROWS * 64)  // 524288 per projection
#define BDN    (B_DIM * D_DIM * N_DIM)   // 32768

// Scratch (device globals: no allocation allowed)
__device__ float g_V[PROJ_ELEMS];
__device__ float g_K[PROJ_ELEMS];
__device__ float g_A[PROJ_ELEMS];
__device__ float g_P[PROJ_ELEMS];        // KP1: localP; KP3: final P
__device__ float g_invP[PROJ_ELEMS];
__device__ float g_chunkProd[NCHUNK * B_DIM * N_DIM];     // 16384
__device__ float g_chunkPrefix[NCHUNK * B_DIM * N_DIM];   // 16384
__device__ float g_Csum[NCHUNK * BDN];   // 1M floats (4MB)

typedef unsigned long long ull;

__device__ __forceinline__ ull pack2(float lo, float hi) {
    ull r; asm("mov.b64 %0, {%1, %2};" : "=l"(r) : "f"(lo), "f"(hi)); return r;
}
__device__ __forceinline__ void unpack2(ull v, float& lo, float& hi) {
    asm("mov.b64 {%0, %1}, %2;" : "=f"(lo), "=f"(hi) : "l"(v));
}
__device__ __forceinline__ void fma2(ull& d, ull a, ull b) {
    asm("fma.rn.f32x2 %0, %1, %2, %0;" : "+l"(d) : "l"(a), "l"(b));
}

// ---------------------------------------------------------------------------
// K1: projections. y = x @ W^T + b  for Wv, Wk, Wa (blockIdx.y selects).
// BM=64, 64 cols, BK=16. 128 threads, each 4 rows x 8 cols as f32x2 pairs.
// x stored DUPLICATED in smem so inner loop = 8 LDS.64 + 16 FFMA2, no movs.
// ---------------------------------------------------------------------------
__global__ void proj_kernel(const float* __restrict__ x,
                            const float* __restrict__ Wv, const float* __restrict__ bv,
                            const float* __restrict__ Wk, const float* __restrict__ bk,
                            const float* __restrict__ Wa, const float* __restrict__ ba)
{
    __shared__ float xs2[16][130];   // duplicated x: [kk][2*r+{0,1}]
    __shared__ float ws[16][72];     // [kk][c]

    const int m = blockIdx.y;
    const float* __restrict__ W    = (m == 0) ? Wv : (m == 1) ? Wk : Wa;
    const float* __restrict__ bias = (m == 0) ? bv : (m == 1) ? bk : ba;
    float* __restrict__ out        = (m == 0) ? g_V : (m == 1) ? g_K : g_A;

    const int row0 = blockIdx.x * 64;
    const int tid  = threadIdx.x;       // 0..127
    const int cg   = tid & 7;           // col group
    const int rg   = tid >> 3;          // row group (0..15)
    const int r_base = rg * 4;
    const int c_base = cg * 8;

    const int lr = tid >> 1;            // 0..63
    const int lk = (tid & 1) * 8;       // 0 or 8

    ull acc[4][4];
    #pragma unroll
    for (int i = 0; i < 4; i++)
        #pragma unroll
        for (int j = 0; j < 4; j++) acc[i][j] = 0ull;

    #pragma unroll 1
    for (int k0 = 0; k0 < IN_DIM; k0 += 16) {
        float4 a0 = *(const float4*)&x[(row0 + lr) * IN_DIM + k0 + lk];
        float4 a1 = *(const float4*)&x[(row0 + lr) * IN_DIM + k0 + lk + 4];
        *(ull*)&xs2[lk + 0][2 * lr] = pack2(a0.x, a0.x);
        *(ull*)&xs2[lk + 1][2 * lr] = pack2(a0.y, a0.y);
        *(ull*)&xs2[lk + 2][2 * lr] = pack2(a0.z, a0.z);
        *(ull*)&xs2[lk + 3][2 * lr] = pack2(a0.w, a0.w);
        *(ull*)&xs2[lk + 4][2 * lr] = pack2(a1.x, a1.x);
        *(ull*)&xs2[lk + 5][2 * lr] = pack2(a1.y, a1.y);
        *(ull*)&xs2[lk + 6][2 * lr] = pack2(a1.z, a1.z);
        *(ull*)&xs2[lk + 7][2 * lr] = pack2(a1.w, a1.w);
        float4 b0 = *(const float4*)&W[lr * IN_DIM + k0 + lk];
        float4 b1 = *(const float4*)&W[lr * IN_DIM + k0 + lk + 4];
        ws[lk + 0][lr] = b0.x; ws[lk + 1][lr] = b0.y;
        ws[lk + 2][lr] = b0.z; ws[lk + 3][lr] = b0.w;
        ws[lk + 4][lr] = b1.x; ws[lk + 5][lr] = b1.y;
        ws[lk + 6][lr] = b1.z; ws[lk + 7][lr] = b1.w;
        __syncthreads();

        #pragma unroll
        for (int kk = 0; kk < 16; kk++) {
            ull xd0 = *(const ull*)&xs2[kk][2 * (r_base + 0)];
            ull xd1 = *(const ull*)&xs2[kk][2 * (r_base + 1)];
            ull xd2 = *(const ull*)&xs2[kk][2 * (r_base + 2)];
            ull xd3 = *(const ull*)&xs2[kk][2 * (r_base + 3)];
            ull w0  = *(const ull*)&ws[kk][c_base + 0];
            ull w1  = *(const ull*)&ws[kk][c_base + 2];
            ull w2  = *(const ull*)&ws[kk][c_base + 4];
            ull w3  = *(const ull*)&ws[kk][c_base + 6];
            fma2(acc[0][0], xd0, w0); fma2(acc[0][1], xd0, w1);
            fma2(acc[0][2], xd0, w2); fma2(acc[0][3], xd0, w3);
            fma2(acc[1][0], xd1, w0); fma2(acc[1][1], xd1, w1);
            fma2(acc[1][2], xd1, w2); fma2(acc[1][3], xd1, w3);
            fma2(acc[2][0], xd2, w0); fma2(acc[2][1], xd2, w1);
            fma2(acc[2][2], xd2, w2); fma2(acc[2][3], xd2, w3);
            fma2(acc[3][0], xd3, w0); fma2(acc[3][1], xd3, w1);
            fma2(acc[3][2], xd3, w2); fma2(acc[3][3], xd3, w3);
        }
        __syncthreads();
    }

    float bb[8];
    #pragma unroll
    for (int j = 0; j < 8; j++) bb[j] = bias[c_base + j];

    #pragma unroll
    for (int i = 0; i < 4; i++) {
        float s[8];
        #pragma unroll
        for (int j = 0; j < 4; j++) unpack2(acc[i][j], s[2 * j], s[2 * j + 1]);
        #pragma unroll
        for (int j = 0; j < 8; j++) s[j] += bb[j];
        if (m == 2) {
            #pragma unroll
            for (int j = 0; j < 8; j++) s[j] = 1.0f / (1.0f + expf(-s[j]));
        }
        int o = (row0 + r_base + i) * 64 + c_base;
        *(float4*)&out[o]     = make_float4(s[0], s[1], s[2], s[3]);
        *(float4*)&out[o + 4] = make_float4(s[4], s[5], s[6], s[7]);
    }
}

// ---------------------------------------------------------------------------
// KP1: within-chunk cumprod of alpha via tile-transpose + warp shfl scan.
// grid 512 = (c, bn_grp), block 1024 (32 warps). Writes localP into g_P and
// whole-chunk product into g_chunkProd.
// ---------------------------------------------------------------------------
__global__ void pscan1_kernel()
{
    __shared__ float s[32][33];
    const int c   = blockIdx.x >> 4;
    const int bn0 = (blockIdx.x & 15) * 32;
    const int w   = threadIdx.x >> 5;
    const int l   = threadIdx.x & 31;
    const int t0  = c * CHUNK;

    // coalesced load: warp w loads t-row (t0+w), 32 consecutive bn
    s[w][l] = g_A[(t0 + w) * 512 + bn0 + l];
    __syncthreads();

    // warp w scans series bn0+w over lane = t
    float p = s[l][w];
    #pragma unroll
    for (int off = 1; off < 32; off <<= 1) {
        float y = __shfl_up_sync(0xffffffffu, p, off);
        if (l >= off) p *= y;
    }
    if (l == 31) g_chunkProd[(c << 9) + bn0 + w] = p;
    s[l][w] = p;               // transpose back (same-thread cell, no race)
    __syncthreads();

    g_P[(t0 + w) * 512 + bn0 + l] = s[w][l];   // localP (coalesced)
}

// ---------------------------------------------------------------------------
// KP2: exclusive product scan of chunk products over c. Warp per (b,n),
// lane = c. grid 16, block 1024.
// ---------------------------------------------------------------------------
__global__ void pscan2_kernel()
{
    const int w  = threadIdx.x >> 5;
    const int l  = threadIdx.x & 31;
    const int bn = blockIdx.x * 32 + w;

    float p = g_chunkProd[(l << 9) + bn];
    #pragma unroll
    for (int off = 1; off < 32; off <<= 1) {
        float y = __shfl_up_sync(0xffffffffu, p, off);
        if (l >= off) p *= y;
    }
    float excl = __shfl_up_sync(0xffffffffu, p, 1);
    if (l == 0) excl = 1.0f;
    g_chunkPrefix[(l << 9) + bn] = excl;
}

// ---------------------------------------------------------------------------
// KP3: elementwise P = prefix * localP, invP = 1/(P+eps). float4, coalesced.
// grid 128, block 1024 (131072 threads x 4 elements).
// ---------------------------------------------------------------------------
__global__ void papply_kernel()
{
    const int idx = blockIdx.x * 1024 + threadIdx.x;  // 0..131071
    const int e   = idx * 4;
    const int c   = e >> 14;          // (e/512)/32
    const int bn  = e & 511;

    float4 lp = *(const float4*)&g_P[e];
    float4 pf = *(const float4*)&g_chunkPrefix[(c << 9) + bn];
    float4 P, iP;
    P.x = pf.x * lp.x;  P.y = pf.y * lp.y;
    P.z = pf.z * lp.z;  P.w = pf.w * lp.w;
    iP.x = 1.0f / (P.x + EPS);  iP.y = 1.0f / (P.y + EPS);
    iP.z = 1.0f / (P.z + EPS);  iP.w = 1.0f / (P.w + EPS);
    *(float4*)&g_P[e]    = P;
    *(float4*)&g_invP[e] = iP;
}

// ---------------------------------------------------------------------------
// K5: per-chunk partial sums of v*k*invP per (b,d,n).
// grid 1024 = (c<<5)|(b<<2)|dt, block 256 = (d_local<<4)|ngroup.
// ---------------------------------------------------------------------------
__global__ void csum_kernel()
{
    int cb = blockIdx.x;
    int dt = cb & 3;
    int b  = (cb >> 2) & 7;
    int c  = cb >> 5;
    int d  = dt * 16 + (threadIdx.x >> 4);
    int n0 = (threadIdx.x & 15) * 4;

    float C0 = 0.f, C1 = 0.f, C2 = 0.f, C3 = 0.f;
    int t0 = c * CHUNK;
    #pragma unroll 4
    for (int i = 0; i < CHUNK; i++) {
        int base = ((t0 + i) * B_DIM + b) * 64;
        float  v  = g_V[base + d];
        float4 kk = *(const float4*)&g_K[base + n0];
        float4 ip = *(const float4*)&g_invP[base + n0];
        C0 = fmaf(v * kk.x, ip.x, C0);
        C1 = fmaf(v * kk.y, ip.y, C1);
        C2 = fmaf(v * kk.z, ip.z, C2);
        C3 = fmaf(v * kk.w, ip.w, C3);
    }
    int o = ((c * B_DIM + b) * D_DIM + d) * N_DIM + n0;
    *(float4*)&g_Csum[o] = make_float4(C0, C1, C2, C3);
}

// ---------------------------------------------------------------------------
// K6: exclusive SUM scan of g_Csum over chunk dim via tile-transpose +
// warp shfl scan. grid 1024, block 1024. In-place.
// ---------------------------------------------------------------------------
__global__ void cscan_kernel()
{
    __shared__ float s[32][33];
    const int bdn0 = blockIdx.x * 32;
    const int w    = threadIdx.x >> 5;
    const int l    = threadIdx.x & 31;

    // coalesced: warp w loads chunk-row c=w, 32 consecutive bdn
    s[w][l] = g_Csum[w * BDN + bdn0 + l];
    __syncthreads();

    float p = s[l][w];
    #pragma unroll
    for (int off = 1; off < 32; off <<= 1) {
        float y = __shfl_up_sync(0xffffffffu, p, off);
        if (l >= off) p += y;
    }
    float excl = __shfl_up_sync(0xffffffffu, p, 1);
    if (l == 0) excl = 0.0f;
    s[l][w] = excl;
    __syncthreads();

    g_Csum[w * BDN + bdn0 + l] = s[w][l];
}

// ---------------------------------------------------------------------------
// K7: final recurrence + output writes.
// out = [ spk (T*B*4096) | mem (T*B*4096) ]
// ---------------------------------------------------------------------------
__global__ void final_kernel(float* __restrict__ out)
{
    int cb = blockIdx.x;
    int dt = cb & 3;
    int b  = (cb >> 2) & 7;
    int c  = cb >> 5;
    int d  = dt * 16 + (threadIdx.x >> 4);
    int n0 = (threadIdx.x & 15) * 4;

    float* __restrict__ spk = out;
    float* __restrict__ mem = out + (size_t)T_DIM * B_DIM * 4096;

    int co = ((c * B_DIM + b) * D_DIM + d) * N_DIM + n0;
    float4 C = *(const float4*)&g_Csum[co];

    int t0 = c * CHUNK;
    #pragma unroll 4
    for (int i = 0; i < CHUNK; i++) {
        int t    = t0 + i;
        int base = (t * B_DIM + b) * 64;
        float  v  = g_V[base + d];
        float4 kk = *(const float4*)&g_K[base + n0];
        float4 ip = *(const float4*)&g_invP[base + n0];
        float4 P4 = *(const float4*)&g_P[base + n0];

        C.x = fmaf(v * kk.x, ip.x, C.x);
        C.y = fmaf(v * kk.y, ip.y, C.y);
        C.z = fmaf(v * kk.z, ip.z, C.z);
        C.w = fmaf(v * kk.w, ip.w, C.w);

        float4 S;
        S.x = C.x * P4.x; S.y = C.y * P4.y;
        S.z = C.z * P4.z; S.w = C.w * P4.w;

        float4 Sp;
        Sp.x = (S.x > 1.0f) ? 1.0f : 0.0f;
        Sp.y = (S.y > 1.0f) ? 1.0f : 0.0f;
        Sp.z = (S.z > 1.0f) ? 1.0f : 0.0f;
        Sp.w = (S.w > 1.0f) ? 1.0f : 0.0f;

        int o = (t * B_DIM + b) * 4096 + d * 64 + n0;
        *(float4*)&mem[o] = S;
        *(float4*)&spk[o] = Sp;
    }
}

// ---------------------------------------------------------------------------
extern "C" void kernel_launch(void* const* d_in, const int* in_sizes, int n_in,
                              void* d_out, int out_size)
{
    const float* x  = (const float*)d_in[0];
    const float* Wv = (const float*)d_in[1];
    const float* bv = (const float*)d_in[2];
    const float* Wk = (const float*)d_in[3];
    const float* bk = (const float*)d_in[4];
    const float* Wa = (const float*)d_in[5];
    const float* ba = (const float*)d_in[6];
    float* out = (float*)d_out;

    proj_kernel<<<dim3(ROWS / 64, 3), 128>>>(x, Wv, bv, Wk, bk, Wa, ba);
    pscan1_kernel<<<NCHUNK * 16, 1024>>>();
    pscan2_kernel<<<16, 1024>>>();
    papply_kernel<<<128, 1024>>>();
    csum_kernel<<<NCHUNK * B_DIM * 4, 256>>>();
    cscan_kernel<<<BDN / 32, 1024>>>();
    final_kernel<<<NCHUNK * B_DIM * 4, 256>>>(out);
}